// round 13
// baseline (speedup 1.0000x reference)
#include <cuda_runtime.h>
#include <cstdint>
#include <cfloat>

#define BB   4
#define CC   64
#define OO   64
#define HH   128
#define WW   128
#define HW   (HH * WW)          // 16384
#define KK   5
#define KK2  (KK * KK)          // 25
#define KROW (CC * KK2)         // 1600
#define PLANE_N (BB * OO)       // 256
#define OUT1 ((size_t)BB * OO * HW)

#define TPB 256
#define PPT 16

// -------- device scratch --------
__device__ float g_s[BB * HW];
__device__ float g_rdn[BB * HW];
__device__ int   g_tap_cnt[OO];
__device__ float g_wsum[OO];
__device__ int   g_tap_k[OO * KROW];
__device__ float g_tap_w[OO * KROW];
__device__ float g_maxv[PLANE_N];

__device__ __forceinline__ void atomicMaxF(float* a, float v) {
    if (v >= 0.f) atomicMax((int*)a, __float_as_int(v));
    else          atomicMin((unsigned int*)a, __float_as_uint(v));
}

// conv over 16 consecutive pixels in row h starting at w0 (16 | 128 -> single row).
__device__ __forceinline__ void conv16(const float* __restrict__ xb, int o, int cnt,
                                       int h, int w0, float* xl,
                                       float* s_w, int* s_ck) {
    #pragma unroll
    for (int u = 0; u < PPT; u++) xl[u] = 0.f;

    if (cnt == 1) {
        int k  = g_tap_k[o * KROW];
        float wt = g_tap_w[o * KROW];
        int c = k / KK2, r = k % KK2;
        int dj = r / KK - 2, dk = r % KK - 2;
        int hh = h + dj;
        if ((unsigned)hh < (unsigned)HH) {
            const float* src = xb + c * HW + hh * WW;
            if (dk == 0) {
                // front-batch 4 independent streaming vector loads
                float4 v0 = __ldcs((const float4*)(src + w0));
                float4 v1 = __ldcs((const float4*)(src + w0 + 4));
                float4 v2 = __ldcs((const float4*)(src + w0 + 8));
                float4 v3 = __ldcs((const float4*)(src + w0 + 12));
                xl[0]  = wt * v0.x; xl[1]  = wt * v0.y; xl[2]  = wt * v0.z; xl[3]  = wt * v0.w;
                xl[4]  = wt * v1.x; xl[5]  = wt * v1.y; xl[6]  = wt * v1.z; xl[7]  = wt * v1.w;
                xl[8]  = wt * v2.x; xl[9]  = wt * v2.y; xl[10] = wt * v2.z; xl[11] = wt * v2.w;
                xl[12] = wt * v3.x; xl[13] = wt * v3.y; xl[14] = wt * v3.z; xl[15] = wt * v3.w;
            } else {
                #pragma unroll
                for (int u = 0; u < PPT; u++) {
                    int ww = w0 + u + dk;
                    if ((unsigned)ww < (unsigned)WW) xl[u] = wt * src[ww];
                }
            }
        }
    } else {
        int ncached = min(cnt, 64);
        for (int t = threadIdx.x; t < ncached; t += TPB) {
            int k = g_tap_k[o * KROW + t];
            int c = k / KK2, r = k % KK2;
            s_ck[t] = (c << 8) | ((r / KK) << 4) | (r % KK);
            s_w[t] = g_tap_w[o * KROW + t];
        }
        __syncthreads();
        for (int t = 0; t < ncached; t++) {
            int pk = s_ck[t];
            float wt = s_w[t];
            int c  = pk >> 8;
            int hh = h + ((pk >> 4) & 15) - 2;
            int dk = (pk & 15) - 2;
            if ((unsigned)hh < (unsigned)HH) {
                const float* src = xb + c * HW + hh * WW;
                #pragma unroll
                for (int u = 0; u < PPT; u++) {
                    int ww = w0 + u + dk;
                    if ((unsigned)ww < (unsigned)WW) xl[u] += wt * src[ww];
                }
            }
        }
        for (int t = 64; t < cnt; t++) {      // rare spill
            int k = g_tap_k[o * KROW + t];
            float wt = g_tap_w[o * KROW + t];
            int c = k / KK2, r = k % KK2;
            int hh = h + r / KK - 2;
            int dk = r % KK - 2;
            if ((unsigned)hh < (unsigned)HH) {
                const float* src = xb + c * HW + hh * WW;
                #pragma unroll
                for (int u = 0; u < PPT; u++) {
                    int ww = w0 + u + dk;
                    if ((unsigned)ww < (unsigned)WW) xl[u] += wt * src[ww];
                }
            }
        }
        __syncthreads();
    }
}

// -------- 1) chansum (blocks 0..255, 4 threads/quad) + sparsify (256..319) + maxv init --------
__global__ void k_chansum(const float* __restrict__ x, const float* __restrict__ Wl) {
    if (blockIdx.x < 256) {
        int t = blockIdx.x * TPB + threadIdx.x;
        if (blockIdx.x == 0) g_maxv[threadIdx.x] = -FLT_MAX;
        int q = t >> 2;
        int part = t & 3;
        int b = q / (HW / 4);
        int qq = q % (HW / 4);
        const float4* xb = (const float4*)(x + (size_t)b * CC * HW) + qq
                           + (size_t)part * 16 * (HW / 4);
        float4 s = make_float4(0.f, 0.f, 0.f, 0.f);
        #pragma unroll
        for (int c = 0; c < 16; c++) {
            float4 v = xb[c * (HW / 4)];
            s.x += v.x; s.y += v.y; s.z += v.z; s.w += v.w;
        }
        #pragma unroll
        for (int off = 1; off <= 2; off <<= 1) {
            s.x += __shfl_xor_sync(0xffffffffu, s.x, off);
            s.y += __shfl_xor_sync(0xffffffffu, s.y, off);
            s.z += __shfl_xor_sync(0xffffffffu, s.z, off);
            s.w += __shfl_xor_sync(0xffffffffu, s.w, off);
        }
        if (part == 0) ((float4*)g_s)[q] = s;
        return;
    }
    if (threadIdx.x >= 32) return;
    int o = blockIdx.x - 256;
    int lane = threadIdx.x;
    const float* row = Wl + o * KROW;
    int base = 0;
    float psum = 0.f;
    for (int k0 = 0; k0 < KROW; k0 += 32) {
        int k = k0 + lane;
        float w = row[k];
        psum += w;
        unsigned m = __ballot_sync(0xffffffffu, w != 0.f);
        if (w != 0.f) {
            int pos = base + __popc(m & ((1u << lane) - 1u));
            g_tap_k[o * KROW + pos] = k;
            g_tap_w[o * KROW + pos] = w;
        }
        base += __popc(m);
    }
    #pragma unroll
    for (int off = 16; off; off >>= 1)
        psum += __shfl_xor_sync(0xffffffffu, psum, off);
    if (lane == 0) { g_tap_cnt[o] = base; g_wsum[o] = psum; }
}

// -------- 2) denom: reciprocal of clamped 5x5 box sum --------
__global__ void k_denom() {
    int i = blockIdx.x * TPB + threadIdx.x;
    int b = i >> 14;
    int p = i & (HW - 1);
    int h = p >> 7, w = p & (WW - 1);
    const float* sb = g_s + b * HW;
    float acc = 0.f;
    #pragma unroll
    for (int dj = -2; dj <= 2; dj++) {
        int hh = h + dj;
        if ((unsigned)hh >= (unsigned)HH) continue;
        #pragma unroll
        for (int dk = -2; dk <= 2; dk++) {
            int ww = w + dk;
            if ((unsigned)ww >= (unsigned)WW) continue;
            acc += sb[hh * WW + ww];
        }
    }
    g_rdn[i] = 1.0f / fmaxf(acc, 5.0f);
}

// -------- 3) main: conv -> out0, plane max of xn1. PPT=16, single wave --------
__global__ __launch_bounds__(TPB, 4) void k_main(const float* __restrict__ x,
                                                 float* __restrict__ out0) {
    int bo = blockIdx.y;
    int b = bo >> 6, o = bo & 63;

    __shared__ float s_w[64];
    __shared__ int   s_ck[64];
    __shared__ float s_red[TPB / 32];

    int cnt = g_tap_cnt[o];
    float inv_ws = 1.f / (1e-10f + g_wsum[o]);
    const float* xb = x + (size_t)b * CC * HW;
    const float* rdn = g_rdn + b * HW;

    int i0 = (blockIdx.x * TPB + threadIdx.x) * PPT;
    int h = i0 >> 7, w0 = i0 & (WW - 1);

    float xl[PPT];
    conv16(xb, o, cnt, h, w0, xl, s_w, s_ck);

    // front-batch rdn loads with the out0 stores following (stores don't block)
    float4 r0 = *(const float4*)(rdn + i0);
    float4 r1 = *(const float4*)(rdn + i0 + 4);
    float4 r2 = *(const float4*)(rdn + i0 + 8);
    float4 r3 = *(const float4*)(rdn + i0 + 12);

    size_t oidx = (size_t)bo * HW + i0;
    *(float4*)(out0 + oidx)      = make_float4(xl[0],  xl[1],  xl[2],  xl[3]);
    *(float4*)(out0 + oidx + 4)  = make_float4(xl[4],  xl[5],  xl[6],  xl[7]);
    *(float4*)(out0 + oidx + 8)  = make_float4(xl[8],  xl[9],  xl[10], xl[11]);
    *(float4*)(out0 + oidx + 12) = make_float4(xl[12], xl[13], xl[14], xl[15]);

    float rd[PPT] = {r0.x, r0.y, r0.z, r0.w, r1.x, r1.y, r1.z, r1.w,
                     r2.x, r2.y, r2.z, r2.w, r3.x, r3.y, r3.z, r3.w};
    float mx = -FLT_MAX;
    #pragma unroll
    for (int u = 0; u < PPT; u++) mx = fmaxf(mx, xl[u] * rd[u] * inv_ws);

    #pragma unroll
    for (int off = 16; off; off >>= 1)
        mx = fmaxf(mx, __shfl_xor_sync(0xffffffffu, mx, off));
    if ((threadIdx.x & 31) == 0) s_red[threadIdx.x >> 5] = mx;
    __syncthreads();
    if (threadIdx.x == 0) {
        float v = s_red[0];
        #pragma unroll
        for (int j = 1; j < TPB / 32; j++) v = fmaxf(v, s_red[j]);
        atomicMaxF(&g_maxv[bo], v);
    }
}

// -------- 4) finalize: front-batched loads, PPT=16, single wave --------
__global__ __launch_bounds__(TPB, 4) void k_final(const float* __restrict__ out0,
                                                  float* __restrict__ out1,
                                                  float* __restrict__ out2) {
    int bo = blockIdx.y;
    int b = bo >> 6, o = bo & 63;
    float sc = (1.f / (1e-10f + g_wsum[o]));
    float rmax = 1.0f / (1e-10f + g_maxv[bo]);
    const float* rdn = g_rdn + b * HW;

    int i0 = (blockIdx.x * TPB + threadIdx.x) * PPT;
    size_t base = (size_t)bo * HW + i0;

    // all 8 loads issued before any compute/store
    float4 a0 = __ldcs((const float4*)(out0 + base));
    float4 a1 = __ldcs((const float4*)(out0 + base + 4));
    float4 a2 = __ldcs((const float4*)(out0 + base + 8));
    float4 a3 = __ldcs((const float4*)(out0 + base + 12));
    float4 r0 = *(const float4*)(rdn + i0);
    float4 r1 = *(const float4*)(rdn + i0 + 4);
    float4 r2 = *(const float4*)(rdn + i0 + 8);
    float4 r3 = *(const float4*)(rdn + i0 + 12);

    float a[PPT] = {a0.x, a0.y, a0.z, a0.w, a1.x, a1.y, a1.z, a1.w,
                    a2.x, a2.y, a2.z, a2.w, a3.x, a3.y, a3.z, a3.w};
    float r[PPT] = {r0.x, r0.y, r0.z, r0.w, r1.x, r1.y, r1.z, r1.w,
                    r2.x, r2.y, r2.z, r2.w, r3.x, r3.y, r3.z, r3.w};

    float v[PPT], bn[PPT];
    #pragma unroll
    for (int u = 0; u < PPT; u++) {
        v[u] = (a[u] * r[u] * sc) * rmax;
        bn[u] = (v[u] * v[u] * v[u] >= 0.5f) ? 1.0f : 0.0f;
    }
    __stcs((float4*)(out1 + base),      make_float4(v[0],  v[1],  v[2],  v[3]));
    __stcs((float4*)(out1 + base + 4),  make_float4(v[4],  v[5],  v[6],  v[7]));
    __stcs((float4*)(out1 + base + 8),  make_float4(v[8],  v[9],  v[10], v[11]));
    __stcs((float4*)(out1 + base + 12), make_float4(v[12], v[13], v[14], v[15]));
    __stcs((float4*)(out2 + base),      make_float4(bn[0],  bn[1],  bn[2],  bn[3]));
    __stcs((float4*)(out2 + base + 4),  make_float4(bn[4],  bn[5],  bn[6],  bn[7]));
    __stcs((float4*)(out2 + base + 8),  make_float4(bn[8],  bn[9],  bn[10], bn[11]));
    __stcs((float4*)(out2 + base + 12), make_float4(bn[12], bn[13], bn[14], bn[15]));
}

extern "C" void kernel_launch(void* const* d_in, const int* in_sizes, int n_in,
                              void* d_out, int out_size) {
    const float* x  = (const float*)d_in[0];
    const float* Wl = (const float*)d_in[1];
    float* out  = (float*)d_out;
    float* out0 = out;
    float* out1 = out + OUT1;
    float* out2 = out + 2 * OUT1;

    k_chansum<<<256 + OO, TPB>>>(x, Wl);               // 320 blocks
    k_denom<<<BB * HW / TPB, TPB>>>();                 // 256 blocks
    dim3 g(HW / (TPB * PPT), PLANE_N);                 // (4, 256) = 1024 blocks, 1 wave
    k_main<<<g, TPB>>>(x, out0);
    k_final<<<g, TPB>>>(out0, out1, out2);
}

// round 15
// speedup vs baseline: 1.1631x; 1.1631x over previous
#include <cuda_runtime.h>
#include <cstdint>
#include <cfloat>

#define BB   4
#define CC   64
#define OO   64
#define HH   128
#define WW   128
#define HW   (HH * WW)          // 16384
#define KK   5
#define KK2  (KK * KK)          // 25
#define KROW (CC * KK2)         // 1600
#define PLANE_N (BB * OO)       // 256
#define OUT1 ((size_t)BB * OO * HW)

#define TPB 256

// -------- device scratch --------
__device__ float g_s[BB * HW];
__device__ float g_rdn[BB * HW];
__device__ int   g_tap_cnt[OO];
__device__ float g_wsum[OO];
__device__ int   g_tap_k[OO * KROW];
__device__ float g_tap_w[OO * KROW];
__device__ float g_maxv[PLANE_N];

__device__ __forceinline__ void atomicMaxF(float* a, float v) {
    if (v >= 0.f) atomicMax((int*)a, __float_as_int(v));
    else          atomicMin((unsigned int*)a, __float_as_uint(v));
}

// conv over 8 consecutive pixels in row h starting at w0 (one row since 8 | 128).
__device__ __forceinline__ void conv8(const float* __restrict__ xb, int o, int cnt,
                                      int h, int w0, float* xl,
                                      float* s_w, int* s_ck) {
    #pragma unroll
    for (int u = 0; u < 8; u++) xl[u] = 0.f;

    if (cnt == 1) {
        int k  = g_tap_k[o * KROW];
        float wt = g_tap_w[o * KROW];
        int c = k / KK2, r = k % KK2;
        int dj = r / KK - 2, dk = r % KK - 2;
        int hh = h + dj;
        if ((unsigned)hh < (unsigned)HH) {
            const float* src = xb + c * HW + hh * WW;
            if (dk == 0) {
                float4 v0 = *(const float4*)(src + w0);
                float4 v1 = *(const float4*)(src + w0 + 4);
                xl[0] = wt * v0.x; xl[1] = wt * v0.y; xl[2] = wt * v0.z; xl[3] = wt * v0.w;
                xl[4] = wt * v1.x; xl[5] = wt * v1.y; xl[6] = wt * v1.z; xl[7] = wt * v1.w;
            } else {
                #pragma unroll
                for (int u = 0; u < 8; u++) {
                    int ww = w0 + u + dk;
                    if ((unsigned)ww < (unsigned)WW) xl[u] = wt * src[ww];
                }
            }
        }
    } else {
        int ncached = min(cnt, 64);
        for (int t = threadIdx.x; t < ncached; t += TPB) {
            int k = g_tap_k[o * KROW + t];
            int c = k / KK2, r = k % KK2;
            s_ck[t] = (c << 8) | ((r / KK) << 4) | (r % KK);
            s_w[t] = g_tap_w[o * KROW + t];
        }
        __syncthreads();
        for (int t = 0; t < ncached; t++) {
            int pk = s_ck[t];
            float wt = s_w[t];
            int c  = pk >> 8;
            int hh = h + ((pk >> 4) & 15) - 2;
            int dk = (pk & 15) - 2;
            if ((unsigned)hh < (unsigned)HH) {
                const float* src = xb + c * HW + hh * WW;
                #pragma unroll
                for (int u = 0; u < 8; u++) {
                    int ww = w0 + u + dk;
                    if ((unsigned)ww < (unsigned)WW) xl[u] += wt * src[ww];
                }
            }
        }
        for (int t = 64; t < cnt; t++) {      // rare spill
            int k = g_tap_k[o * KROW + t];
            float wt = g_tap_w[o * KROW + t];
            int c = k / KK2, r = k % KK2;
            int hh = h + r / KK - 2;
            int dk = r % KK - 2;
            if ((unsigned)hh < (unsigned)HH) {
                const float* src = xb + c * HW + hh * WW;
                #pragma unroll
                for (int u = 0; u < 8; u++) {
                    int ww = w0 + u + dk;
                    if ((unsigned)ww < (unsigned)WW) xl[u] += wt * src[ww];
                }
            }
        }
        __syncthreads();
    }
}

// -------- 1) chansum (blocks 0..255, 4 threads/quad) + sparsify (256..319) + maxv init --------
__global__ void k_chansum(const float* __restrict__ x, const float* __restrict__ Wl) {
    if (blockIdx.x < 256) {
        int t = blockIdx.x * TPB + threadIdx.x;
        if (blockIdx.x == 0) g_maxv[threadIdx.x] = -FLT_MAX;
        int q = t >> 2;
        int part = t & 3;
        int b = q / (HW / 4);
        int qq = q % (HW / 4);
        const float4* xb = (const float4*)(x + (size_t)b * CC * HW) + qq
                           + (size_t)part * 16 * (HW / 4);
        float4 s = make_float4(0.f, 0.f, 0.f, 0.f);
        #pragma unroll
        for (int c = 0; c < 16; c++) {
            float4 v = xb[c * (HW / 4)];
            s.x += v.x; s.y += v.y; s.z += v.z; s.w += v.w;
        }
        #pragma unroll
        for (int off = 1; off <= 2; off <<= 1) {
            s.x += __shfl_xor_sync(0xffffffffu, s.x, off);
            s.y += __shfl_xor_sync(0xffffffffu, s.y, off);
            s.z += __shfl_xor_sync(0xffffffffu, s.z, off);
            s.w += __shfl_xor_sync(0xffffffffu, s.w, off);
        }
        if (part == 0) ((float4*)g_s)[q] = s;
        return;
    }
    if (threadIdx.x >= 32) return;
    int o = blockIdx.x - 256;
    int lane = threadIdx.x;
    const float* row = Wl + o * KROW;
    int base = 0;
    float psum = 0.f;
    for (int k0 = 0; k0 < KROW; k0 += 32) {
        int k = k0 + lane;
        float w = row[k];
        psum += w;
        unsigned m = __ballot_sync(0xffffffffu, w != 0.f);
        if (w != 0.f) {
            int pos = base + __popc(m & ((1u << lane) - 1u));
            g_tap_k[o * KROW + pos] = k;
            g_tap_w[o * KROW + pos] = w;
        }
        base += __popc(m);
    }
    #pragma unroll
    for (int off = 16; off; off >>= 1)
        psum += __shfl_xor_sync(0xffffffffu, psum, off);
    if (lane == 0) { g_tap_cnt[o] = base; g_wsum[o] = psum; }
}

// -------- 2) denom: separable 5x5 box via smem. One block = 2 plane rows --------
__global__ __launch_bounds__(TPB) void k_denom() {
    // block handles rows [h0, h0+1] of plane b; 256 blocks total
    int rp = blockIdx.x;                 // row-pair index 0..255
    int b  = rp >> 6;                    // 64 row-pairs per batch
    int h0 = (rp & 63) * 2;
    const float* sb = g_s + b * HW;

    __shared__ float s_in[6][WW];        // chansum rows h0-2 .. h0+3 (zero padded)
    __shared__ float s_hs[6][WW];        // horizontal 5-sums

    // load 6 rows, 768 values, 3 per thread
    #pragma unroll
    for (int it = 0; it < 3; it++) {
        int idx = it * TPB + threadIdx.x;     // 0..767
        int lr = idx >> 7;                    // local row 0..5
        int w  = idx & (WW - 1);
        int gh = h0 - 2 + lr;
        s_in[lr][w] = ((unsigned)gh < (unsigned)HH) ? sb[gh * WW + w] : 0.f;
    }
    __syncthreads();

    // horizontal 5-tap (zero OOB), 3 per thread
    #pragma unroll
    for (int it = 0; it < 3; it++) {
        int idx = it * TPB + threadIdx.x;
        int lr = idx >> 7;
        int w  = idx & (WW - 1);
        float a = 0.f;
        #pragma unroll
        for (int dk = -2; dk <= 2; dk++) {
            int ww = w + dk;
            if ((unsigned)ww < (unsigned)WW) a += s_in[lr][ww];
        }
        s_hs[lr][w] = a;
    }
    __syncthreads();

    // vertical 5-tap for my pixel: thread t -> row tr = t>>7 (0/1), col t&127
    int tr = threadIdx.x >> 7;
    int w  = threadIdx.x & (WW - 1);
    float acc = s_hs[tr][w] + s_hs[tr + 1][w] + s_hs[tr + 2][w]
              + s_hs[tr + 3][w] + s_hs[tr + 4][w];
    g_rdn[b * HW + (h0 + tr) * WW + w] = 1.0f / fmaxf(acc, 5.0f);
}

// -------- 3) main: conv -> out0 only, plane max of xn1 --------
__global__ __launch_bounds__(TPB) void k_main(const float* __restrict__ x,
                                              float* __restrict__ out0) {
    int bo = blockIdx.y;
    int b = bo >> 6, o = bo & 63;

    __shared__ float s_w[64];
    __shared__ int   s_ck[64];
    __shared__ float s_red[TPB / 32];

    int cnt = g_tap_cnt[o];
    float inv_ws = 1.f / (1e-10f + g_wsum[o]);
    const float* xb = x + (size_t)b * CC * HW;
    const float* rdn = g_rdn + b * HW;

    int i0 = (blockIdx.x * TPB + threadIdx.x) * 8;
    int h = i0 >> 7, w0 = i0 & (WW - 1);

    float xl[8];
    conv8(xb, o, cnt, h, w0, xl, s_w, s_ck);

    size_t oidx = (size_t)bo * HW + i0;
    *(float4*)(out0 + oidx)     = make_float4(xl[0], xl[1], xl[2], xl[3]);
    *(float4*)(out0 + oidx + 4) = make_float4(xl[4], xl[5], xl[6], xl[7]);

    float4 r0 = *(const float4*)(rdn + i0);
    float4 r1 = *(const float4*)(rdn + i0 + 4);
    float rd[8] = {r0.x, r0.y, r0.z, r0.w, r1.x, r1.y, r1.z, r1.w};
    float mx = -FLT_MAX;
    #pragma unroll
    for (int u = 0; u < 8; u++) mx = fmaxf(mx, xl[u] * rd[u] * inv_ws);

    #pragma unroll
    for (int off = 16; off; off >>= 1)
        mx = fmaxf(mx, __shfl_xor_sync(0xffffffffu, mx, off));
    if ((threadIdx.x & 31) == 0) s_red[threadIdx.x >> 5] = mx;
    __syncthreads();
    if (threadIdx.x == 0) {
        float v = s_red[0];
        #pragma unroll
        for (int j = 1; j < TPB / 32; j++) v = fmaxf(v, s_red[j]);
        atomicMaxF(&g_maxv[bo], v);
    }
}

// -------- 4) finalize: read out0+rdn (L2-hot), write out1/out2 streaming. PPT=8 --------
__global__ __launch_bounds__(TPB) void k_final(const float* __restrict__ out0,
                                               float* __restrict__ out1,
                                               float* __restrict__ out2) {
    int bo = blockIdx.y;
    int b = bo >> 6, o = bo & 63;
    float inv_ws = 1.f / (1e-10f + g_wsum[o]);
    float rmax = 1.0f / (1e-10f + g_maxv[bo]);
    const float* rdn = g_rdn + b * HW;

    int i0 = (blockIdx.x * TPB + threadIdx.x) * 8;
    size_t base = (size_t)bo * HW + i0;

    float4 a0 = *(const float4*)(out0 + base);
    float4 a1 = *(const float4*)(out0 + base + 4);
    float4 r0 = *(const float4*)(rdn + i0);
    float4 r1 = *(const float4*)(rdn + i0 + 4);

    float v0 = (a0.x * r0.x * inv_ws) * rmax;
    float v1 = (a0.y * r0.y * inv_ws) * rmax;
    float v2 = (a0.z * r0.z * inv_ws) * rmax;
    float v3 = (a0.w * r0.w * inv_ws) * rmax;
    float v4 = (a1.x * r1.x * inv_ws) * rmax;
    float v5 = (a1.y * r1.y * inv_ws) * rmax;
    float v6 = (a1.z * r1.z * inv_ws) * rmax;
    float v7 = (a1.w * r1.w * inv_ws) * rmax;

    __stcs((float4*)(out1 + base),     make_float4(v0, v1, v2, v3));
    __stcs((float4*)(out1 + base + 4), make_float4(v4, v5, v6, v7));

    float4 b0, b1;
    b0.x = (v0 * v0 * v0 >= 0.5f) ? 1.0f : 0.0f;
    b0.y = (v1 * v1 * v1 >= 0.5f) ? 1.0f : 0.0f;
    b0.z = (v2 * v2 * v2 >= 0.5f) ? 1.0f : 0.0f;
    b0.w = (v3 * v3 * v3 >= 0.5f) ? 1.0f : 0.0f;
    b1.x = (v4 * v4 * v4 >= 0.5f) ? 1.0f : 0.0f;
    b1.y = (v5 * v5 * v5 >= 0.5f) ? 1.0f : 0.0f;
    b1.z = (v6 * v6 * v6 >= 0.5f) ? 1.0f : 0.0f;
    b1.w = (v7 * v7 * v7 >= 0.5f) ? 1.0f : 0.0f;
    __stcs((float4*)(out2 + base),     b0);
    __stcs((float4*)(out2 + base + 4), b1);
}

extern "C" void kernel_launch(void* const* d_in, const int* in_sizes, int n_in,
                              void* d_out, int out_size) {
    const float* x  = (const float*)d_in[0];
    const float* Wl = (const float*)d_in[1];
    float* out  = (float*)d_out;
    float* out0 = out;
    float* out1 = out + OUT1;
    float* out2 = out + 2 * OUT1;

    k_chansum<<<256 + OO, TPB>>>(x, Wl);               // 320 blocks
    k_denom<<<256, TPB>>>();                           // 256 blocks, separable box
    dim3 g(HW / (TPB * 8), PLANE_N);                   // (8, 256) = 2048 blocks
    k_main<<<g, TPB>>>(x, out0);
    k_final<<<g, TPB>>>(out0, out1, out2);
}